// round 10
// baseline (speedup 1.0000x reference)
#include <cuda_runtime.h>
#include <math.h>
#include <stdint.h>

#define N 512
#define N2 (N*N)
#define BATCH 128
#define NMAT 129           // 128 batch matrices + 1 for L0
#define EPSF 1e-7f
#define NPAN 16

typedef unsigned long long u64;

// packed f32x2 FMA (Blackwell FFMA2 — only reachable via PTX)
__device__ __forceinline__ u64 ffma2(u64 a, u64 b, u64 c) {
    u64 d;
    asm("fma.rn.f32x2 %0, %1, %2, %3;" : "=l"(d) : "l"(a), "l"(b), "l"(c));
    return d;
}
__device__ __forceinline__ u64 pack_dup(float a) {
    u64 d; unsigned int u = __float_as_uint(a);
    asm("mov.b64 %0, {%1, %1};" : "=l"(d) : "r"(u));
    return d;
}

// ---------------- device scratch (no allocations allowed) ----------------
__device__ float g_C[4 * N2];                                   // 4 planes, 4 MB
__device__ __align__(16) float g_M[(size_t)NMAT * N2 + 64];     // 129 matrices
__device__ __align__(16) float g_Lp[(size_t)NMAT * 32 * N];     // -L21, [mat][k*512+r]
__device__ __align__(16) float g_Up[(size_t)NMAT * 32 * N];     // +U12, [mat][k*512+c]
__device__ float g_ld[NMAT * NPAN];                             // per-panel logdet

// ---------------- kernel 1: IPF + plane construction ----------------
__global__ void k_ipf(const float* __restrict__ W, const float* __restrict__ Vc,
                      const float* __restrict__ Ec) {
    int p = blockIdx.x * blockDim.x + threadIdx.x;
    int i = p >> 9;
    int j = p & (N - 1);

    float4 e4 = reinterpret_cast<const float4*>(Ec)[p];
    float e00 = expf(e4.x), e01 = expf(e4.y), e10 = expf(e4.z), e11 = expf(e4.w);
    float inv = 1.0f / (e00 + e01 + e10 + e11);
    e00 *= inv; e01 *= inv; e10 *= inv; e11 *= inv;

    float a0 = Vc[2*i], a1 = Vc[2*i+1];
    float mi = fmaxf(a0, a1);
    float xa0 = expf(a0 - mi), xa1 = expf(a1 - mi);
    float di = 1.0f / (xa0 + xa1);
    float vi0 = xa0 * di, vi1 = xa1 * di;

    float b0 = Vc[2*j], b1 = Vc[2*j+1];
    float mj = fmaxf(b0, b1);
    float xb0 = expf(b0 - mj), xb1 = expf(b1 - mj);
    float dj = 1.0f / (xb0 + xb1);
    float vj0 = xb0 * dj, vj1 = xb1 * dj;

    #pragma unroll
    for (int it = 0; it < 10; it++) {
        float r0 = e00 + e01 + EPSF, r1 = e10 + e11 + EPSF;
        float c0 = e00 + e10 + EPSF, c1 = e01 + e11 + EPSF;
        float f0 = vi0 / r0, f1 = vi1 / r1;
        e00 *= f0; e01 *= f0; e10 *= f1; e11 *= f1;
        float g0 = vj0 / c0, g1 = vj1 / c1;
        e00 *= g0; e10 *= g0; e01 *= g1; e11 *= g1;
        float iv = 1.0f / (e00 + e01 + e10 + e11 + EPSF);
        e00 *= iv; e01 *= iv; e10 *= iv; e11 *= iv;
    }

    float wm = 0.0f;
    if (i != j) {
        float w = (i > j) ? W[i*N + j] : W[j*N + i];
        wm = 1.0f / (1.0f + expf(-w));
    } else {
        e00 = e01 = e10 = e11 = 0.0f;
    }
    e00 = fminf(fmaxf(e00, 0.0f), 1.0f);
    e01 = fminf(fmaxf(e01, 0.0f), 1.0f);
    e10 = fminf(fmaxf(e10, 0.0f), 1.0f);
    e11 = fminf(fmaxf(e11, 0.0f), 1.0f);

    g_C[0*N2 + p] = wm * e00 / (vi0 * vj0);
    g_C[1*N2 + p] = wm * e01 / (vi0 * vj1);
    g_C[2*N2 + p] = wm * e10 / (vi1 * vj0);
    g_C[3*N2 + p] = wm * e11 / (vi1 * vj1);
}

// ---------------- kernel 2: build padded 512x512 Laplacians ----------------
__global__ void __launch_bounds__(512, 1) k_build(const int* __restrict__ x,
                                                  const float* __restrict__ W) {
    __shared__ int sx[N];
    const int batch = blockIdx.x;
    const int tid   = threadIdx.x;
    float* Mb = g_M + (size_t)batch * N2;

    if (batch < BATCH) {
        for (int t = tid; t < N; t += 512) sx[t] = x[batch*N + t];
    }
    __syncthreads();

    int w = tid >> 5, lane = tid & 31;
    for (int r = w; r < N; r += 16) {
        if (r == N - 1) {
            for (int c = lane; c < N; c += 32) Mb[r*N + c] = (c == N-1) ? 1.0f : 0.0f;
            continue;
        }
        int i = r + 1;
        float sum = 0.0f;
        if (batch < BATCH) {
            int xi = sx[i];
            const float* p0 = g_C + (size_t)(xi*2) * N2 + (size_t)i * N;
            const float* p1 = p0 + N2;
            for (int j = lane; j < N; j += 32) {
                float v0 = p0[j], v1 = p1[j];
                float v = sx[j] ? v1 : v0;
                sum += v;
                int c = j - 1;
                if (j > 0 && c != r) Mb[r*N + c] = -v;
            }
        } else {
            for (int j = lane; j < N; j += 32) {
                float v = 0.0f;
                if (j != i) {
                    float wv = (i > j) ? W[i*N + j] : W[j*N + i];
                    v = 1.0f / (1.0f + expf(-wv));
                }
                sum += v;
                int c = j - 1;
                if (j > 0 && c != r) Mb[r*N + c] = -v;
            }
        }
        #pragma unroll
        for (int off = 16; off; off >>= 1) sum += __shfl_xor_sync(0xffffffffu, sum, off);
        if (lane == 0) { Mb[r*N + r] = sum; Mb[r*N + (N-1)] = 0.0f; }
    }
}

// ---------------- kernel 3: panel factor (4 CTAs per matrix) ----------------
// blockIdx.x = matrix, blockIdx.y = quarter q (0..3)
// threads 0..127: L21 rows idx = q*128+tid; threads 128..255: U12 cols
__global__ void __launch_bounds__(256) k_panel(int kb) {
    __shared__ float sD[32*33];
    __shared__ float sDinv[32];
    const int mat = blockIdx.x;
    const int q   = blockIdx.y;
    const int tid = threadIdx.x;
    float* Mb = g_M + (size_t)mat * N2;
    float* Lp = g_Lp + (size_t)mat * 32 * N;
    float* Up = g_Up + (size_t)mat * 32 * N;
    const int j0 = kb * 32, j1 = j0 + 32;
    const int m = N - j1;

    // warp 0: register LU of the 32x32 diagonal block (redundant per CTA)
    if (tid < 32) {
        const int lane = tid;
        float v[32];
        const float4* rp = reinterpret_cast<const float4*>(&Mb[(size_t)(j0+lane)*N + j0]);
        #pragma unroll
        for (int qq = 0; qq < 8; qq++) {
            float4 t4 = rp[qq];
            v[4*qq]=t4.x; v[4*qq+1]=t4.y; v[4*qq+2]=t4.z; v[4*qq+3]=t4.w;
        }
        #pragma unroll
        for (int j = 0; j < 32; j++) {
            float diag = __shfl_sync(0xffffffffu, v[j], j);
            float l = v[j] * (1.0f / diag);
            #pragma unroll
            for (int c = j + 1; c < 32; c++) {
                float ujc = __shfl_sync(0xffffffffu, v[c], j);
                if (lane > j) v[c] -= l * ujc;
            }
            if (lane > j) v[j] = l;
        }
        if (q == 0) {
            float ld = logf(fabsf(v[lane]));
            #pragma unroll
            for (int off = 16; off; off >>= 1) ld += __shfl_xor_sync(0xffffffffu, ld, off);
            if (lane == 0) g_ld[mat*NPAN + kb] = ld;
        }
        #pragma unroll
        for (int c = 0; c < 32; c++) sD[lane*33 + c] = v[c];
        sDinv[lane] = 1.0f / v[lane];
    }
    __syncthreads();

    if (tid < 128) {
        // ---- L21 row: solve l * U11 = A21_row; store NEGATED ----
        const int idx = q*128 + tid;
        if (idx < m) {
            const int r = j1 + idx;
            float a[32];
            const float4* rp = reinterpret_cast<const float4*>(&Mb[(size_t)r*N + j0]);
            #pragma unroll
            for (int qq = 0; qq < 8; qq++) {
                float4 t4 = rp[qq];
                a[4*qq]=t4.x; a[4*qq+1]=t4.y; a[4*qq+2]=t4.z; a[4*qq+3]=t4.w;
            }
            #pragma unroll
            for (int k = 0; k < 32; k++) {
                float acc = a[k];
                #pragma unroll
                for (int t = 0; t < k; t++) acc -= a[t] * sD[t*33 + k];
                a[k] = acc * sDinv[k];
            }
            #pragma unroll
            for (int k = 0; k < 32; k++) Lp[k*N + r] = -a[k];
        }
    } else {
        // ---- U12 col: forward substitution; store PLAIN ----
        const int idx = q*128 + (tid - 128);
        if (idx < m) {
            const int c = j1 + idx;
            float y[32];
            #pragma unroll
            for (int k = 0; k < 32; k++) y[k] = Mb[(size_t)(j0+k)*N + c];
            #pragma unroll
            for (int k = 1; k < 32; k++) {
                float acc = y[k];
                #pragma unroll
                for (int t = 0; t < k; t++) acc -= sD[k*33 + t] * y[t];
                y[k] = acc;
            }
            #pragma unroll
            for (int k = 0; k < 32; k++) Up[k*N + c] = y[k];
        }
    }
}

// ---------------- kernel 4: trailing update, 128x128 tile per CTA, occ 2 ----------------
// Inner loop per k: 2 broadcast LDS.128 (scalar -L) + 8 pack_dup MOV (alu pipe)
// + 2 LDS.128 (U cols) + 32 FFMA2.  Issue ~44, crossbar ~10 cyc per warp-k.
#define TL_ST 132          // smem row stride (floats), 16B multiple
#define SMEM_UPD (2 * 32 * TL_ST * 4)

__global__ void __launch_bounds__(256, 2) k_update(int kb) {
    extern __shared__ float smf[];
    float* sL = smf;                    // [k][rr] -L21 rows of this tile
    float* sU = smf + 32*TL_ST;         // [k][cc] +U12 cols of this tile

    const int mat = blockIdx.z;
    const int j1  = kb * 32 + 32;
    const int m   = N - j1;
    const int c0t = blockIdx.x * 128;
    const int r0t = blockIdx.y * 128;
    float* Mb = g_M + (size_t)mat * N2;
    const float* Lp = g_Lp + (size_t)mat * 32 * N;
    const float* Up = g_Up + (size_t)mat * 32 * N;
    const int tid = threadIdx.x;
    const int tx = tid & 15, ty = tid >> 4;

    // stage -L rows and U cols for this tile (coalesced)
    for (int idx = tid; idx < 32*128; idx += 256) {
        int k = idx >> 7, qq = idx & 127;
        sL[k*TL_ST + qq] = (r0t + qq < m) ? Lp[k*N + (j1 + r0t + qq)] : 0.0f;
        sU[k*TL_ST + qq] = (c0t + qq < m) ? Up[k*N + (j1 + c0t + qq)] : 0.0f;
    }
    __syncthreads();

    const int r0 = r0t + ty*8;          // relative to j1
    const int c0 = c0t + tx*8;
    if (r0 < m && c0 < m) {             // multiples of 8 within m (mult of 32)
        const int ra = j1 + r0;
        const int ca = j1 + c0;
        u64 acc[8][4];
        #pragma unroll
        for (int ii = 0; ii < 8; ii++) {
            const ulonglong2* src = reinterpret_cast<const ulonglong2*>(
                &Mb[(size_t)(ra+ii)*N + ca]);
            ulonglong2 u0 = src[0], u1 = src[1];
            acc[ii][0]=u0.x; acc[ii][1]=u0.y; acc[ii][2]=u1.x; acc[ii][3]=u1.y;
        }
        #pragma unroll 8
        for (int k = 0; k < 32; k++) {
            const float4* apf = reinterpret_cast<const float4*>(&sL[k*TL_ST + ty*8]);
            float4 aA = apf[0], aB = apf[1];
            const ulonglong2* bp = reinterpret_cast<const ulonglong2*>(&sU[k*TL_ST + tx*8]);
            ulonglong2 b0 = bp[0], b1 = bp[1];
            float af[8] = {aA.x, aA.y, aA.z, aA.w, aB.x, aB.y, aB.z, aB.w};
            #pragma unroll
            for (int ii = 0; ii < 8; ii++) {
                u64 a2 = pack_dup(af[ii]);
                acc[ii][0] = ffma2(a2, b0.x, acc[ii][0]);
                acc[ii][1] = ffma2(a2, b0.y, acc[ii][1]);
                acc[ii][2] = ffma2(a2, b1.x, acc[ii][2]);
                acc[ii][3] = ffma2(a2, b1.y, acc[ii][3]);
            }
        }
        #pragma unroll
        for (int ii = 0; ii < 8; ii++) {
            ulonglong2* dst = reinterpret_cast<ulonglong2*>(&Mb[(size_t)(ra+ii)*N + ca]);
            ulonglong2 o0, o1;
            o0.x = acc[ii][0]; o0.y = acc[ii][1];
            o1.x = acc[ii][2]; o1.y = acc[ii][3];
            dst[0] = o0; dst[1] = o1;
        }
    }
}

// ---------------- kernel 5: combine ----------------
__global__ void k_final(const int* __restrict__ x, const float* __restrict__ Vc,
                        float* __restrict__ out) {
    __shared__ float red[256];
    int b = blockIdx.x, tid = threadIdx.x;
    float s = 0.0f;
    for (int i = tid; i < N; i += 256) {
        int xi = x[b*N + i];
        float a0 = Vc[2*i], a1 = Vc[2*i+1];
        float m = fmaxf(a0, a1);
        float lse = m + logf(expf(a0 - m) + expf(a1 - m));
        s += (xi ? a1 : a0) - lse;
    }
    red[tid] = s;
    __syncthreads();
    #pragma unroll
    for (int o = 128; o; o >>= 1) {
        if (tid < o) red[tid] += red[tid + o];
        __syncthreads();
    }
    if (tid == 0) {
        float ld = 0.0f;
        #pragma unroll
        for (int k = 0; k < NPAN; k++)
            ld += g_ld[b*NPAN + k] - g_ld[BATCH*NPAN + k];
        out[b] = red[0] + ld;
    }
}

// ---------------- launcher ----------------
extern "C" void kernel_launch(void* const* d_in, const int* in_sizes, int n_in,
                              void* d_out, int out_size) {
    const int* x = nullptr;
    const float* W = nullptr;
    const float* Vc = nullptr;
    const float* Ec = nullptr;
    for (int k = 0; k < n_in; k++) {
        switch (in_sizes[k]) {
            case BATCH * N:   x  = (const int*)d_in[k];   break;  // 65536
            case N * N:       W  = (const float*)d_in[k]; break;  // 262144
            case N * 2:       Vc = (const float*)d_in[k]; break;  // 1024
            case N * N * 4:   Ec = (const float*)d_in[k]; break;  // 1048576
        }
    }
    float* out = (float*)d_out;

    cudaFuncSetAttribute(k_update, cudaFuncAttributeMaxDynamicSharedMemorySize, SMEM_UPD);

    k_ipf<<<N2 / 256, 256>>>(W, Vc, Ec);
    k_build<<<NMAT, 512>>>(x, W);
    for (int kb = 0; kb < NPAN; kb++) {
        dim3 pg(NMAT, 4);
        k_panel<<<pg, 256>>>(kb);
        int m = N - 32*(kb+1);
        if (m > 0) {
            int nt = (m + 127) / 128;
            dim3 ug(nt, nt, NMAT);
            k_update<<<ug, 256, SMEM_UPD>>>(kb);
        }
    }
    k_final<<<BATCH, 256>>>(x, Vc, out);
}

// round 11
// speedup vs baseline: 1.0815x; 1.0815x over previous
#include <cuda_runtime.h>
#include <math.h>
#include <stdint.h>

#define N 512
#define N2 (N*N)
#define BATCH 128
#define NMAT 129           // 128 batch matrices + 1 for L0
#define EPSF 1e-7f
#define NPAN 16
#define KB_HEAD 9          // panels 0..8 via multi-kernel; 9..15 in k_tail

typedef unsigned long long u64;

// packed f32x2 FMA (Blackwell FFMA2 — only reachable via PTX)
__device__ __forceinline__ u64 ffma2(u64 a, u64 b, u64 c) {
    u64 d;
    asm("fma.rn.f32x2 %0, %1, %2, %3;" : "=l"(d) : "l"(a), "l"(b), "l"(c));
    return d;
}
__device__ __forceinline__ u64 pack_dup(float a) {
    u64 d; unsigned int u = __float_as_uint(a);
    asm("mov.b64 %0, {%1, %1};" : "=l"(d) : "r"(u));
    return d;
}

// ---------------- device scratch (no allocations allowed) ----------------
__device__ float g_C[4 * N2];                                   // 4 planes, 4 MB
__device__ __align__(16) float g_M[(size_t)NMAT * N2 + 64];     // 129 matrices
__device__ __align__(16) float g_Lp[(size_t)NMAT * 32 * N];     // -L21, [mat][k*512+r]
__device__ __align__(16) float g_Up[(size_t)NMAT * 32 * N];     // +U12, [mat][k*512+c]
__device__ float g_ld[NMAT * NPAN];                             // per-panel logdet

// ---------------- kernel 1: IPF + plane construction ----------------
__global__ void k_ipf(const float* __restrict__ W, const float* __restrict__ Vc,
                      const float* __restrict__ Ec) {
    int p = blockIdx.x * blockDim.x + threadIdx.x;
    int i = p >> 9;
    int j = p & (N - 1);

    float4 e4 = reinterpret_cast<const float4*>(Ec)[p];
    float e00 = expf(e4.x), e01 = expf(e4.y), e10 = expf(e4.z), e11 = expf(e4.w);
    float inv = 1.0f / (e00 + e01 + e10 + e11);
    e00 *= inv; e01 *= inv; e10 *= inv; e11 *= inv;

    float a0 = Vc[2*i], a1 = Vc[2*i+1];
    float mi = fmaxf(a0, a1);
    float xa0 = expf(a0 - mi), xa1 = expf(a1 - mi);
    float di = 1.0f / (xa0 + xa1);
    float vi0 = xa0 * di, vi1 = xa1 * di;

    float b0 = Vc[2*j], b1 = Vc[2*j+1];
    float mj = fmaxf(b0, b1);
    float xb0 = expf(b0 - mj), xb1 = expf(b1 - mj);
    float dj = 1.0f / (xb0 + xb1);
    float vj0 = xb0 * dj, vj1 = xb1 * dj;

    #pragma unroll
    for (int it = 0; it < 10; it++) {
        float r0 = e00 + e01 + EPSF, r1 = e10 + e11 + EPSF;
        float c0 = e00 + e10 + EPSF, c1 = e01 + e11 + EPSF;
        float f0 = vi0 / r0, f1 = vi1 / r1;
        e00 *= f0; e01 *= f0; e10 *= f1; e11 *= f1;
        float g0 = vj0 / c0, g1 = vj1 / c1;
        e00 *= g0; e10 *= g0; e01 *= g1; e11 *= g1;
        float iv = 1.0f / (e00 + e01 + e10 + e11 + EPSF);
        e00 *= iv; e01 *= iv; e10 *= iv; e11 *= iv;
    }

    float wm = 0.0f;
    if (i != j) {
        float w = (i > j) ? W[i*N + j] : W[j*N + i];
        wm = 1.0f / (1.0f + expf(-w));
    } else {
        e00 = e01 = e10 = e11 = 0.0f;
    }
    e00 = fminf(fmaxf(e00, 0.0f), 1.0f);
    e01 = fminf(fmaxf(e01, 0.0f), 1.0f);
    e10 = fminf(fmaxf(e10, 0.0f), 1.0f);
    e11 = fminf(fmaxf(e11, 0.0f), 1.0f);

    g_C[0*N2 + p] = wm * e00 / (vi0 * vj0);
    g_C[1*N2 + p] = wm * e01 / (vi0 * vj1);
    g_C[2*N2 + p] = wm * e10 / (vi1 * vj0);
    g_C[3*N2 + p] = wm * e11 / (vi1 * vj1);
}

// ---------------- kernel 2: build padded 512x512 Laplacians ----------------
__global__ void __launch_bounds__(512, 1) k_build(const int* __restrict__ x,
                                                  const float* __restrict__ W) {
    __shared__ int sx[N];
    const int batch = blockIdx.x;
    const int tid   = threadIdx.x;
    float* Mb = g_M + (size_t)batch * N2;

    if (batch < BATCH) {
        for (int t = tid; t < N; t += 512) sx[t] = x[batch*N + t];
    }
    __syncthreads();

    int w = tid >> 5, lane = tid & 31;
    for (int r = w; r < N; r += 16) {
        if (r == N - 1) {
            for (int c = lane; c < N; c += 32) Mb[r*N + c] = (c == N-1) ? 1.0f : 0.0f;
            continue;
        }
        int i = r + 1;
        float sum = 0.0f;
        if (batch < BATCH) {
            int xi = sx[i];
            const float* p0 = g_C + (size_t)(xi*2) * N2 + (size_t)i * N;
            const float* p1 = p0 + N2;
            for (int j = lane; j < N; j += 32) {
                float v0 = p0[j], v1 = p1[j];
                float v = sx[j] ? v1 : v0;
                sum += v;
                int c = j - 1;
                if (j > 0 && c != r) Mb[r*N + c] = -v;
            }
        } else {
            for (int j = lane; j < N; j += 32) {
                float v = 0.0f;
                if (j != i) {
                    float wv = (i > j) ? W[i*N + j] : W[j*N + i];
                    v = 1.0f / (1.0f + expf(-wv));
                }
                sum += v;
                int c = j - 1;
                if (j > 0 && c != r) Mb[r*N + c] = -v;
            }
        }
        #pragma unroll
        for (int off = 16; off; off >>= 1) sum += __shfl_xor_sync(0xffffffffu, sum, off);
        if (lane == 0) { Mb[r*N + r] = sum; Mb[r*N + (N-1)] = 0.0f; }
    }
}

// ---------------- kernel 3: panel factor (4 CTAs per matrix) ----------------
__global__ void __launch_bounds__(256) k_panel(int kb) {
    __shared__ float sD[32*33];
    __shared__ float sDinv[32];
    const int mat = blockIdx.x;
    const int q   = blockIdx.y;
    const int tid = threadIdx.x;
    float* Mb = g_M + (size_t)mat * N2;
    float* Lp = g_Lp + (size_t)mat * 32 * N;
    float* Up = g_Up + (size_t)mat * 32 * N;
    const int j0 = kb * 32, j1 = j0 + 32;
    const int m = N - j1;

    if (tid < 32) {
        const int lane = tid;
        float v[32];
        const float4* rp = reinterpret_cast<const float4*>(&Mb[(size_t)(j0+lane)*N + j0]);
        #pragma unroll
        for (int qq = 0; qq < 8; qq++) {
            float4 t4 = rp[qq];
            v[4*qq]=t4.x; v[4*qq+1]=t4.y; v[4*qq+2]=t4.z; v[4*qq+3]=t4.w;
        }
        #pragma unroll
        for (int j = 0; j < 32; j++) {
            float diag = __shfl_sync(0xffffffffu, v[j], j);
            float l = v[j] * (1.0f / diag);
            #pragma unroll
            for (int c = j + 1; c < 32; c++) {
                float ujc = __shfl_sync(0xffffffffu, v[c], j);
                if (lane > j) v[c] -= l * ujc;
            }
            if (lane > j) v[j] = l;
        }
        if (q == 0) {
            float ld = logf(fabsf(v[lane]));
            #pragma unroll
            for (int off = 16; off; off >>= 1) ld += __shfl_xor_sync(0xffffffffu, ld, off);
            if (lane == 0) g_ld[mat*NPAN + kb] = ld;
        }
        #pragma unroll
        for (int c = 0; c < 32; c++) sD[lane*33 + c] = v[c];
        sDinv[lane] = 1.0f / v[lane];
    }
    __syncthreads();

    if (tid < 128) {
        const int idx = q*128 + tid;
        if (idx < m) {
            const int r = j1 + idx;
            float a[32];
            const float4* rp = reinterpret_cast<const float4*>(&Mb[(size_t)r*N + j0]);
            #pragma unroll
            for (int qq = 0; qq < 8; qq++) {
                float4 t4 = rp[qq];
                a[4*qq]=t4.x; a[4*qq+1]=t4.y; a[4*qq+2]=t4.z; a[4*qq+3]=t4.w;
            }
            #pragma unroll
            for (int k = 0; k < 32; k++) {
                float acc = a[k];
                #pragma unroll
                for (int t = 0; t < k; t++) acc -= a[t] * sD[t*33 + k];
                a[k] = acc * sDinv[k];
            }
            #pragma unroll
            for (int k = 0; k < 32; k++) Lp[k*N + r] = -a[k];
        }
    } else {
        const int idx = q*128 + (tid - 128);
        if (idx < m) {
            const int c = j1 + idx;
            float y[32];
            #pragma unroll
            for (int k = 0; k < 32; k++) y[k] = Mb[(size_t)(j0+k)*N + c];
            #pragma unroll
            for (int k = 1; k < 32; k++) {
                float acc = y[k];
                #pragma unroll
                for (int t = 0; t < k; t++) acc -= sD[k*33 + t] * y[t];
                y[k] = acc;
            }
            #pragma unroll
            for (int k = 0; k < 32; k++) Up[k*N + c] = y[k];
        }
    }
}

// ---------------- kernel 4: trailing update, 128x64 tile, occupancy 4 ----------------
#define TL_L 132           // L row stride (u64 units)
#define TL_U 68            // U row stride (floats)
#define SMEM_UPD (32*TL_L*8 + 32*TL_U*4)

__global__ void __launch_bounds__(256, 4) k_update(int kb) {
    extern __shared__ char smraw[];
    u64*   sLd = (u64*)smraw;                  // [k][rr] duplicated -L21 (128 rows)
    float* sUu = (float*)(sLd + 32*TL_L);      // [k][cc] U12 (64 cols)

    const int mat = blockIdx.x;
    const int j1  = kb * 32 + 32;
    const int m   = N - j1;
    const int r0t = blockIdx.y * 128;
    const int c0t = blockIdx.z * 64;
    float* Mb = g_M + (size_t)mat * N2;
    const float* Lp = g_Lp + (size_t)mat * 32 * N;
    const float* Up = g_Up + (size_t)mat * 32 * N;
    const int tid = threadIdx.x;
    const int tx = tid & 15, ty = tid >> 4;

    for (int idx = tid; idx < 32*128; idx += 256) {
        int k = idx >> 7, qq = idx & 127;
        float lv = (r0t + qq < m) ? Lp[k*N + (j1 + r0t + qq)] : 0.0f;
        sLd[k*TL_L + qq] = pack_dup(lv);
    }
    for (int idx = tid; idx < 32*64; idx += 256) {
        int k = idx >> 6, qq = idx & 63;
        float uv = (c0t + qq < m) ? Up[k*N + (j1 + c0t + qq)] : 0.0f;
        sUu[k*TL_U + qq] = uv;
    }
    __syncthreads();

    const int r0 = r0t + ty*8;          // relative to j1
    const int c0 = c0t + tx*4;
    if (r0 < m && c0 < m) {
        const int ra = j1 + r0;
        const int ca = j1 + c0;
        u64 acc[8][2];
        #pragma unroll
        for (int ii = 0; ii < 8; ii++) {
            ulonglong2 v = *reinterpret_cast<const ulonglong2*>(&Mb[(size_t)(ra+ii)*N + ca]);
            acc[ii][0] = v.x; acc[ii][1] = v.y;
        }
        #pragma unroll 8
        for (int k = 0; k < 32; k++) {
            const ulonglong2* ap = reinterpret_cast<const ulonglong2*>(&sLd[k*TL_L + ty*8]);
            ulonglong2 a01 = ap[0], a23 = ap[1], a45 = ap[2], a67 = ap[3];
            ulonglong2 b = *reinterpret_cast<const ulonglong2*>(&sUu[k*TL_U + tx*4]);
            acc[0][0]=ffma2(a01.x,b.x,acc[0][0]); acc[0][1]=ffma2(a01.x,b.y,acc[0][1]);
            acc[1][0]=ffma2(a01.y,b.x,acc[1][0]); acc[1][1]=ffma2(a01.y,b.y,acc[1][1]);
            acc[2][0]=ffma2(a23.x,b.x,acc[2][0]); acc[2][1]=ffma2(a23.x,b.y,acc[2][1]);
            acc[3][0]=ffma2(a23.y,b.x,acc[3][0]); acc[3][1]=ffma2(a23.y,b.y,acc[3][1]);
            acc[4][0]=ffma2(a45.x,b.x,acc[4][0]); acc[4][1]=ffma2(a45.x,b.y,acc[4][1]);
            acc[5][0]=ffma2(a45.y,b.x,acc[5][0]); acc[5][1]=ffma2(a45.y,b.y,acc[5][1]);
            acc[6][0]=ffma2(a67.x,b.x,acc[6][0]); acc[6][1]=ffma2(a67.x,b.y,acc[6][1]);
            acc[7][0]=ffma2(a67.y,b.x,acc[7][0]); acc[7][1]=ffma2(a67.y,b.y,acc[7][1]);
        }
        #pragma unroll
        for (int ii = 0; ii < 8; ii++) {
            ulonglong2 o; o.x = acc[ii][0]; o.y = acc[ii][1];
            *reinterpret_cast<ulonglong2*>(&Mb[(size_t)(ra+ii)*N + ca]) = o;
        }
    }
}

// ---------------- kernel 5: tail LU — trailing 224x224 entirely in smem ----------------
#define TOFF 288
#define TM 224
#define TST 228            // smem row stride (floats)
#define SMEM_TAIL ((TM*TST + 32*33 + 32) * 4)

__global__ void __launch_bounds__(256) k_tail() {
    extern __shared__ float sA[];
    float* sD    = sA + TM*TST;
    float* sDinv = sD + 32*33;
    const int mat = blockIdx.x;
    const int tid = threadIdx.x;
    const int tx = tid & 15, ty = tid >> 4;
    float* Mb = g_M + (size_t)mat * N2;

    // load trailing 224x224 block into smem (coalesced float4 per row)
    for (int e = tid; e < TM * (TM/4); e += 256) {
        int r = e / (TM/4), c4 = e % (TM/4);
        float4 v = *reinterpret_cast<const float4*>(&Mb[(size_t)(TOFF+r)*N + TOFF + c4*4]);
        *reinterpret_cast<float4*>(&sA[r*TST + c4*4]) = v;
    }
    __syncthreads();

    for (int p = 0; p < 7; p++) {
        const int j0 = p*32, j1 = j0 + 32;
        const int m = TM - j1;

        // warp 0: register LU of 32x32 diag block (from smem)
        if (tid < 32) {
            const int lane = tid;
            float v[32];
            #pragma unroll
            for (int c = 0; c < 32; c++) v[c] = sA[(j0+lane)*TST + j0 + c];
            #pragma unroll
            for (int j = 0; j < 32; j++) {
                float diag = __shfl_sync(0xffffffffu, v[j], j);
                float l = v[j] * (1.0f / diag);
                #pragma unroll
                for (int c = j + 1; c < 32; c++) {
                    float ujc = __shfl_sync(0xffffffffu, v[c], j);
                    if (lane > j) v[c] -= l * ujc;
                }
                if (lane > j) v[j] = l;
            }
            float ld = logf(fabsf(v[lane]));
            #pragma unroll
            for (int off = 16; off; off >>= 1) ld += __shfl_xor_sync(0xffffffffu, ld, off);
            if (lane == 0) g_ld[mat*NPAN + KB_HEAD + p] = ld;
            #pragma unroll
            for (int c = 0; c < 32; c++) sD[lane*33 + c] = v[c];
            sDinv[lane] = 1.0f / v[lane];
        }
        __syncthreads();
        if (m == 0) break;

        // L21 rows (one thread per row) and U12 cols (one thread per col); m <= 192
        if (tid < m) {
            const int r = j1 + tid;
            float a[32];
            #pragma unroll
            for (int k = 0; k < 32; k++) a[k] = sA[r*TST + j0 + k];
            #pragma unroll
            for (int k = 0; k < 32; k++) {
                float acc = a[k];
                #pragma unroll
                for (int t = 0; t < k; t++) acc -= a[t] * sD[t*33 + k];
                a[k] = acc * sDinv[k];
            }
            #pragma unroll
            for (int k = 0; k < 32; k++) sA[r*TST + j0 + k] = a[k];

            const int c = j1 + tid;
            float y[32];
            #pragma unroll
            for (int k = 0; k < 32; k++) y[k] = sA[(j0+k)*TST + c];
            #pragma unroll
            for (int k = 1; k < 32; k++) {
                float acc = y[k];
                #pragma unroll
                for (int t = 0; t < k; t++) acc -= sD[k*33 + t] * y[t];
                y[k] = acc;
            }
            #pragma unroll
            for (int k = 0; k < 32; k++) sA[(j0+k)*TST + c] = y[k];
        }
        __syncthreads();

        // GEMM in smem: C -= L21 * U12 (8x8 per thread)
        for (int rb = 0; rb < m; rb += 128) {
            for (int cb = 0; cb < m; cb += 128) {
                const int r0 = rb + ty*8, c0 = cb + tx*8;
                if (r0 < m && c0 < m) {
                    float acc[8][8];
                    #pragma unroll
                    for (int ii = 0; ii < 8; ii++) {
                        const float4* cp = reinterpret_cast<const float4*>(
                            &sA[(j1+r0+ii)*TST + j1 + c0]);
                        float4 v0 = cp[0], v1 = cp[1];
                        acc[ii][0]=v0.x; acc[ii][1]=v0.y; acc[ii][2]=v0.z; acc[ii][3]=v0.w;
                        acc[ii][4]=v1.x; acc[ii][5]=v1.y; acc[ii][6]=v1.z; acc[ii][7]=v1.w;
                    }
                    #pragma unroll 4
                    for (int k = 0; k < 32; k++) {
                        const float4* bp = reinterpret_cast<const float4*>(
                            &sA[(j0+k)*TST + j1 + c0]);
                        float4 b0 = bp[0], b1 = bp[1];
                        float bf[8] = {b0.x,b0.y,b0.z,b0.w,b1.x,b1.y,b1.z,b1.w};
                        #pragma unroll
                        for (int ii = 0; ii < 8; ii++) {
                            float na = -sA[(j1+r0+ii)*TST + j0 + k];
                            #pragma unroll
                            for (int jj = 0; jj < 8; jj++)
                                acc[ii][jj] = fmaf(na, bf[jj], acc[ii][jj]);
                        }
                    }
                    #pragma unroll
                    for (int ii = 0; ii < 8; ii++) {
                        float4* cp = reinterpret_cast<float4*>(
                            &sA[(j1+r0+ii)*TST + j1 + c0]);
                        float4 o0 = make_float4(acc[ii][0],acc[ii][1],acc[ii][2],acc[ii][3]);
                        float4 o1 = make_float4(acc[ii][4],acc[ii][5],acc[ii][6],acc[ii][7]);
                        cp[0] = o0; cp[1] = o1;
                    }
                }
            }
        }
        __syncthreads();
    }
}

// ---------------- kernel 6: combine ----------------
__global__ void k_final(const int* __restrict__ x, const float* __restrict__ Vc,
                        float* __restrict__ out) {
    __shared__ float red[256];
    int b = blockIdx.x, tid = threadIdx.x;
    float s = 0.0f;
    for (int i = tid; i < N; i += 256) {
        int xi = x[b*N + i];
        float a0 = Vc[2*i], a1 = Vc[2*i+1];
        float m = fmaxf(a0, a1);
        float lse = m + logf(expf(a0 - m) + expf(a1 - m));
        s += (xi ? a1 : a0) - lse;
    }
    red[tid] = s;
    __syncthreads();
    #pragma unroll
    for (int o = 128; o; o >>= 1) {
        if (tid < o) red[tid] += red[tid + o];
        __syncthreads();
    }
    if (tid == 0) {
        float ld = 0.0f;
        #pragma unroll
        for (int k = 0; k < NPAN; k++)
            ld += g_ld[b*NPAN + k] - g_ld[BATCH*NPAN + k];
        out[b] = red[0] + ld;
    }
}

// ---------------- launcher ----------------
extern "C" void kernel_launch(void* const* d_in, const int* in_sizes, int n_in,
                              void* d_out, int out_size) {
    const int* x = nullptr;
    const float* W = nullptr;
    const float* Vc = nullptr;
    const float* Ec = nullptr;
    for (int k = 0; k < n_in; k++) {
        switch (in_sizes[k]) {
            case BATCH * N:   x  = (const int*)d_in[k];   break;  // 65536
            case N * N:       W  = (const float*)d_in[k]; break;  // 262144
            case N * 2:       Vc = (const float*)d_in[k]; break;  // 1024
            case N * N * 4:   Ec = (const float*)d_in[k]; break;  // 1048576
        }
    }
    float* out = (float*)d_out;

    cudaFuncSetAttribute(k_update, cudaFuncAttributeMaxDynamicSharedMemorySize, SMEM_UPD);
    cudaFuncSetAttribute(k_tail,   cudaFuncAttributeMaxDynamicSharedMemorySize, SMEM_TAIL);

    k_ipf<<<N2 / 256, 256>>>(W, Vc, Ec);
    k_build<<<NMAT, 512>>>(x, W);
    for (int kb = 0; kb < KB_HEAD; kb++) {
        dim3 pg(NMAT, 4);
        k_panel<<<pg, 256>>>(kb);
        int m = N - 32*(kb+1);
        dim3 ug(NMAT, (m + 127)/128, (m + 63)/64);
        k_update<<<ug, 256, SMEM_UPD>>>(kb);
    }
    k_tail<<<NMAT, 256, SMEM_TAIL>>>();
    k_final<<<BATCH, 256>>>(x, Vc, out);
}

// round 12
// speedup vs baseline: 1.1799x; 1.0910x over previous
#include <cuda_runtime.h>
#include <math.h>
#include <stdint.h>

#define N 512
#define N2 (N*N)
#define BATCH 128
#define NMAT 129           // 128 batch matrices + 1 for L0
#define EPSF 1e-7f
#define NPAN 16

typedef unsigned long long u64;

// packed f32x2 FMA (Blackwell FFMA2 — only reachable via PTX)
__device__ __forceinline__ u64 ffma2(u64 a, u64 b, u64 c) {
    u64 d;
    asm("fma.rn.f32x2 %0, %1, %2, %3;" : "=l"(d) : "l"(a), "l"(b), "l"(c));
    return d;
}
__device__ __forceinline__ u64 pack_dup(float a) {
    u64 d; unsigned int u = __float_as_uint(a);
    asm("mov.b64 %0, {%1, %1};" : "=l"(d) : "r"(u));
    return d;
}

// ---------------- device scratch (no allocations allowed) ----------------
__device__ float g_C[4 * N2];                                   // 4 planes, 4 MB
__device__ __align__(16) float g_M[(size_t)NMAT * N2 + 64];     // 129 matrices
__device__ __align__(16) float g_Lp[(size_t)NMAT * 64 * N];     // -L, [mat][k*512+r], k<32: A, k>=32: B
__device__ __align__(16) float g_Up[(size_t)NMAT * 64 * N];     // +U, same layout
__device__ float g_ld[NMAT * NPAN];                             // per-panel logdet

// ---------------- kernel 1: IPF + plane construction ----------------
__global__ void k_ipf(const float* __restrict__ W, const float* __restrict__ Vc,
                      const float* __restrict__ Ec) {
    int p = blockIdx.x * blockDim.x + threadIdx.x;
    int i = p >> 9;
    int j = p & (N - 1);

    float4 e4 = reinterpret_cast<const float4*>(Ec)[p];
    float e00 = expf(e4.x), e01 = expf(e4.y), e10 = expf(e4.z), e11 = expf(e4.w);
    float inv = 1.0f / (e00 + e01 + e10 + e11);
    e00 *= inv; e01 *= inv; e10 *= inv; e11 *= inv;

    float a0 = Vc[2*i], a1 = Vc[2*i+1];
    float mi = fmaxf(a0, a1);
    float xa0 = expf(a0 - mi), xa1 = expf(a1 - mi);
    float di = 1.0f / (xa0 + xa1);
    float vi0 = xa0 * di, vi1 = xa1 * di;

    float b0 = Vc[2*j], b1 = Vc[2*j+1];
    float mj = fmaxf(b0, b1);
    float xb0 = expf(b0 - mj), xb1 = expf(b1 - mj);
    float dj = 1.0f / (xb0 + xb1);
    float vj0 = xb0 * dj, vj1 = xb1 * dj;

    #pragma unroll
    for (int it = 0; it < 10; it++) {
        float r0 = e00 + e01 + EPSF, r1 = e10 + e11 + EPSF;
        float c0 = e00 + e10 + EPSF, c1 = e01 + e11 + EPSF;
        float f0 = vi0 / r0, f1 = vi1 / r1;
        e00 *= f0; e01 *= f0; e10 *= f1; e11 *= f1;
        float g0 = vj0 / c0, g1 = vj1 / c1;
        e00 *= g0; e10 *= g0; e01 *= g1; e11 *= g1;
        float iv = 1.0f / (e00 + e01 + e10 + e11 + EPSF);
        e00 *= iv; e01 *= iv; e10 *= iv; e11 *= iv;
    }

    float wm = 0.0f;
    if (i != j) {
        float w = (i > j) ? W[i*N + j] : W[j*N + i];
        wm = 1.0f / (1.0f + expf(-w));
    } else {
        e00 = e01 = e10 = e11 = 0.0f;
    }
    e00 = fminf(fmaxf(e00, 0.0f), 1.0f);
    e01 = fminf(fmaxf(e01, 0.0f), 1.0f);
    e10 = fminf(fmaxf(e10, 0.0f), 1.0f);
    e11 = fminf(fmaxf(e11, 0.0f), 1.0f);

    g_C[0*N2 + p] = wm * e00 / (vi0 * vj0);
    g_C[1*N2 + p] = wm * e01 / (vi0 * vj1);
    g_C[2*N2 + p] = wm * e10 / (vi1 * vj0);
    g_C[3*N2 + p] = wm * e11 / (vi1 * vj1);
}

// ---------------- kernel 2: build padded 512x512 Laplacians ----------------
__global__ void __launch_bounds__(512, 1) k_build(const int* __restrict__ x,
                                                  const float* __restrict__ W) {
    __shared__ int sx[N];
    const int batch = blockIdx.x;
    const int tid   = threadIdx.x;
    float* Mb = g_M + (size_t)batch * N2;

    if (batch < BATCH) {
        for (int t = tid; t < N; t += 512) sx[t] = x[batch*N + t];
    }
    __syncthreads();

    int w = tid >> 5, lane = tid & 31;
    for (int r = w; r < N; r += 16) {
        if (r == N - 1) {
            for (int c = lane; c < N; c += 32) Mb[r*N + c] = (c == N-1) ? 1.0f : 0.0f;
            continue;
        }
        int i = r + 1;
        float sum = 0.0f;
        if (batch < BATCH) {
            int xi = sx[i];
            const float* p0 = g_C + (size_t)(xi*2) * N2 + (size_t)i * N;
            const float* p1 = p0 + N2;
            for (int j = lane; j < N; j += 32) {
                float v0 = p0[j], v1 = p1[j];
                float v = sx[j] ? v1 : v0;
                sum += v;
                int c = j - 1;
                if (j > 0 && c != r) Mb[r*N + c] = -v;
            }
        } else {
            for (int j = lane; j < N; j += 32) {
                float v = 0.0f;
                if (j != i) {
                    float wv = (i > j) ? W[i*N + j] : W[j*N + i];
                    v = 1.0f / (1.0f + expf(-wv));
                }
                sum += v;
                int c = j - 1;
                if (j > 0 && c != r) Mb[r*N + c] = -v;
            }
        }
        #pragma unroll
        for (int off = 16; off; off >>= 1) sum += __shfl_xor_sync(0xffffffffu, sum, off);
        if (lane == 0) { Mb[r*N + r] = sum; Mb[r*N + (N-1)] = 0.0f; }
    }
}

// ---------------- kernel 3: panel factor (A-role / standalone), slot A ----------------
__global__ void __launch_bounds__(256) k_panel(int kb) {
    __shared__ float sD[32*33];
    __shared__ float sDinv[32];
    const int mat = blockIdx.x;
    const int q   = blockIdx.y;
    const int tid = threadIdx.x;
    float* Mb = g_M + (size_t)mat * N2;
    float* Lp = g_Lp + (size_t)mat * 64 * N;
    float* Up = g_Up + (size_t)mat * 64 * N;
    const int j0 = kb * 32, j1 = j0 + 32;
    const int m = N - j1;

    if (tid < 32) {
        const int lane = tid;
        float v[32];
        const float4* rp = reinterpret_cast<const float4*>(&Mb[(size_t)(j0+lane)*N + j0]);
        #pragma unroll
        for (int qq = 0; qq < 8; qq++) {
            float4 t4 = rp[qq];
            v[4*qq]=t4.x; v[4*qq+1]=t4.y; v[4*qq+2]=t4.z; v[4*qq+3]=t4.w;
        }
        #pragma unroll
        for (int j = 0; j < 32; j++) {
            float diag = __shfl_sync(0xffffffffu, v[j], j);
            float l = v[j] * (1.0f / diag);
            #pragma unroll
            for (int c = j + 1; c < 32; c++) {
                float ujc = __shfl_sync(0xffffffffu, v[c], j);
                if (lane > j) v[c] -= l * ujc;
            }
            if (lane > j) v[j] = l;
        }
        if (q == 0) {
            float ld = logf(fabsf(v[lane]));
            #pragma unroll
            for (int off = 16; off; off >>= 1) ld += __shfl_xor_sync(0xffffffffu, ld, off);
            if (lane == 0) g_ld[mat*NPAN + kb] = ld;
        }
        #pragma unroll
        for (int c = 0; c < 32; c++) sD[lane*33 + c] = v[c];
        sDinv[lane] = 1.0f / v[lane];
    }
    __syncthreads();

    if (tid < 128) {
        const int idx = q*128 + tid;
        if (idx < m) {
            const int r = j1 + idx;
            float a[32];
            const float4* rp = reinterpret_cast<const float4*>(&Mb[(size_t)r*N + j0]);
            #pragma unroll
            for (int qq = 0; qq < 8; qq++) {
                float4 t4 = rp[qq];
                a[4*qq]=t4.x; a[4*qq+1]=t4.y; a[4*qq+2]=t4.z; a[4*qq+3]=t4.w;
            }
            #pragma unroll
            for (int k = 0; k < 32; k++) {
                float acc = a[k];
                #pragma unroll
                for (int t = 0; t < k; t++) acc -= a[t] * sD[t*33 + k];
                a[k] = acc * sDinv[k];
            }
            #pragma unroll
            for (int k = 0; k < 32; k++) Lp[k*N + r] = -a[k];
        }
    } else {
        const int idx = q*128 + (tid - 128);
        if (idx < m) {
            const int c = j1 + idx;
            float y[32];
            #pragma unroll
            for (int k = 0; k < 32; k++) y[k] = Mb[(size_t)(j0+k)*N + c];
            #pragma unroll
            for (int k = 1; k < 32; k++) {
                float acc = y[k];
                #pragma unroll
                for (int t = 0; t < 32 && t < k; t++) acc -= sD[k*33 + t] * y[t];
                y[k] = acc;
            }
            #pragma unroll
            for (int k = 0; k < 32; k++) Up[k*N + c] = y[k];
        }
    }
}

// ---------------- kernel 3b: panel B of a pair — fuses panel A's rank-32 fix ----------------
// j0 = 64p+32. True values A' = A + nL_A * U_A (nL_A stored negated).
// Writes -L_B / +U_B to slot B (k offsets 32..63).
__global__ void __launch_bounds__(256) k_panelB(int p) {
    __shared__ float sLA[32*33];   // nL_A[j0+i][t]      -> [i*33+t]
    __shared__ float sUA[32*33];   // U_A[t][j0+c]       -> [t*33+c]
    __shared__ float sD[32*33];
    __shared__ float sDinv[32];
    const int mat = blockIdx.x;
    const int q   = blockIdx.y;
    const int tid = threadIdx.x;
    float* Mb = g_M + (size_t)mat * N2;
    float* Lp = g_Lp + (size_t)mat * 64 * N;
    float* Up = g_Up + (size_t)mat * 64 * N;
    const int j0 = 64*p + 32, j1 = j0 + 32;
    const int m = N - j1;

    // stage the 32x32 nL_A rows and U_A cols of the strip
    for (int e = tid; e < 1024; e += 256) {
        int i = e >> 5, t = e & 31;
        sLA[i*33 + t] = Lp[t*N + (j0 + i)];
        sUA[t*33 + i] = Up[t*N + (j0 + i)];
    }
    __syncthreads();

    // warp 0: fused diag block + register LU
    if (tid < 32) {
        const int lane = tid;
        float v[32];
        const float4* rp = reinterpret_cast<const float4*>(&Mb[(size_t)(j0+lane)*N + j0]);
        #pragma unroll
        for (int qq = 0; qq < 8; qq++) {
            float4 t4 = rp[qq];
            v[4*qq]=t4.x; v[4*qq+1]=t4.y; v[4*qq+2]=t4.z; v[4*qq+3]=t4.w;
        }
        #pragma unroll 4
        for (int t = 0; t < 32; t++) {
            float nl = sLA[lane*33 + t];
            #pragma unroll
            for (int c = 0; c < 32; c++) v[c] += nl * sUA[t*33 + c];
        }
        #pragma unroll
        for (int j = 0; j < 32; j++) {
            float diag = __shfl_sync(0xffffffffu, v[j], j);
            float l = v[j] * (1.0f / diag);
            #pragma unroll
            for (int c = j + 1; c < 32; c++) {
                float ujc = __shfl_sync(0xffffffffu, v[c], j);
                if (lane > j) v[c] -= l * ujc;
            }
            if (lane > j) v[j] = l;
        }
        if (q == 0) {
            float ld = logf(fabsf(v[lane]));
            #pragma unroll
            for (int off = 16; off; off >>= 1) ld += __shfl_xor_sync(0xffffffffu, ld, off);
            if (lane == 0) g_ld[mat*NPAN + 2*p + 1] = ld;
        }
        #pragma unroll
        for (int c = 0; c < 32; c++) sD[lane*33 + c] = v[c];
        sDinv[lane] = 1.0f / v[lane];
    }
    __syncthreads();

    if (tid < 128) {
        // L_B row r: fused fix then solve against U11_B
        const int idx = q*128 + tid;
        if (idx < m) {
            const int r = j1 + idx;
            float a[32];
            const float4* rp = reinterpret_cast<const float4*>(&Mb[(size_t)r*N + j0]);
            #pragma unroll
            for (int qq = 0; qq < 8; qq++) {
                float4 t4 = rp[qq];
                a[4*qq]=t4.x; a[4*qq+1]=t4.y; a[4*qq+2]=t4.z; a[4*qq+3]=t4.w;
            }
            float nla[32];
            #pragma unroll
            for (int t = 0; t < 32; t++) nla[t] = Lp[t*N + r];
            #pragma unroll 4
            for (int t = 0; t < 32; t++) {
                float nl = nla[t];
                #pragma unroll
                for (int k = 0; k < 32; k++) a[k] += nl * sUA[t*33 + k];
            }
            #pragma unroll
            for (int k = 0; k < 32; k++) {
                float acc = a[k];
                #pragma unroll
                for (int t = 0; t < k; t++) acc -= a[t] * sD[t*33 + k];
                a[k] = acc * sDinv[k];
            }
            #pragma unroll
            for (int k = 0; k < 32; k++) Lp[(32+k)*N + r] = -a[k];
        }
    } else {
        // U_B col c: fused fix then forward substitution
        const int idx = q*128 + (tid - 128);
        if (idx < m) {
            const int c = j1 + idx;
            float y[32];
            #pragma unroll
            for (int k = 0; k < 32; k++) y[k] = Mb[(size_t)(j0+k)*N + c];
            float ua[32];
            #pragma unroll
            for (int t = 0; t < 32; t++) ua[t] = Up[t*N + c];
            #pragma unroll 4
            for (int t = 0; t < 32; t++) {
                float u = ua[t];
                #pragma unroll
                for (int k = 0; k < 32; k++) y[k] += sLA[k*33 + t] * u;
            }
            #pragma unroll
            for (int k = 1; k < 32; k++) {
                float acc = y[k];
                #pragma unroll
                for (int t = 0; t < 32 && t < k; t++) acc -= sD[k*33 + t] * y[t];
                y[k] = acc;
            }
            #pragma unroll
            for (int k = 0; k < 32; k++) Up[(32+k)*N + c] = y[k];
        }
    }
}

// ---------------- kernel 4: rank-64 trailing update, 128x64 tile, occ 4 ----------------
#define TL64 132           // sL row stride (floats)
#define TU64 68            // sU row stride (floats)
#define SMEM_U64 ((64*TL64 + 64*TU64) * 4)    // 51200 B -> 4 CTAs/SM

__global__ void __launch_bounds__(256, 4) k_update64(int p) {
    extern __shared__ float smf[];
    float* sL = smf;                    // [k][rr] -L (A then B)
    float* sU = smf + 64*TL64;          // [k][cc] +U (A then B)

    const int mat = blockIdx.x;
    const int j1  = 64*p + 64;
    const int m   = N - j1;
    const int r0t = blockIdx.y * 128;
    const int c0t = blockIdx.z * 64;
    float* Mb = g_M + (size_t)mat * N2;
    const float* Lp = g_Lp + (size_t)mat * 64 * N;
    const float* Up = g_Up + (size_t)mat * 64 * N;
    const int tid = threadIdx.x;
    const int tx = tid & 15, ty = tid >> 4;

    for (int idx = tid; idx < 64*128; idx += 256) {
        int k = idx >> 7, qq = idx & 127;
        sL[k*TL64 + qq] = (r0t + qq < m) ? Lp[k*N + (j1 + r0t + qq)] : 0.0f;
    }
    for (int idx = tid; idx < 64*64; idx += 256) {
        int k = idx >> 6, qq = idx & 63;
        sU[k*TU64 + qq] = (c0t + qq < m) ? Up[k*N + (j1 + c0t + qq)] : 0.0f;
    }
    __syncthreads();

    const int r0 = r0t + ty*8;
    const int c0 = c0t + tx*4;
    if (r0 < m) {                       // cols always in range (m multiple of 64)
        const int ra = j1 + r0;
        const int ca = j1 + c0;
        u64 acc[8][2];
        #pragma unroll
        for (int ii = 0; ii < 8; ii++) {
            ulonglong2 v = *reinterpret_cast<const ulonglong2*>(&Mb[(size_t)(ra+ii)*N + ca]);
            acc[ii][0] = v.x; acc[ii][1] = v.y;
        }
        #pragma unroll 8
        for (int k = 0; k < 64; k++) {
            const float4* apf = reinterpret_cast<const float4*>(&sL[k*TL64 + ty*8]);
            float4 aA = apf[0], aB = apf[1];
            ulonglong2 b = *reinterpret_cast<const ulonglong2*>(&sU[k*TU64 + tx*4]);
            float af[8] = {aA.x, aA.y, aA.z, aA.w, aB.x, aB.y, aB.z, aB.w};
            #pragma unroll
            for (int ii = 0; ii < 8; ii++) {
                u64 a2 = pack_dup(af[ii]);
                acc[ii][0] = ffma2(a2, b.x, acc[ii][0]);
                acc[ii][1] = ffma2(a2, b.y, acc[ii][1]);
            }
        }
        #pragma unroll
        for (int ii = 0; ii < 8; ii++) {
            ulonglong2 o; o.x = acc[ii][0]; o.y = acc[ii][1];
            *reinterpret_cast<ulonglong2*>(&Mb[(size_t)(ra+ii)*N + ca]) = o;
        }
    }
}

// ---------------- kernel 4b: rank-32 update (only for kb=8), occ 4 ----------------
#define TL_L 132
#define TL_U 68
#define SMEM_UPD (32*TL_L*8 + 32*TL_U*4)

__global__ void __launch_bounds__(256, 4) k_update(int kb) {
    extern __shared__ char smraw[];
    u64*   sLd = (u64*)smraw;
    float* sUu = (float*)(sLd + 32*TL_L);

    const int mat = blockIdx.x;
    const int j1  = kb * 32 + 32;
    const int m   = N - j1;
    const int r0t = blockIdx.y * 128;
    const int c0t = blockIdx.z * 64;
    float* Mb = g_M + (size_t)mat * N2;
    const float* Lp = g_Lp + (size_t)mat * 64 * N;
    const float* Up = g_Up + (size_t)mat * 64 * N;
    const int tid = threadIdx.x;
    const int tx = tid & 15, ty = tid >> 4;

    for (int idx = tid; idx < 32*128; idx += 256) {
        int k = idx >> 7, qq = idx & 127;
        float lv = (r0t + qq < m) ? Lp[k*N + (j1 + r0t + qq)] : 0.0f;
        sLd[k*TL_L + qq] = pack_dup(lv);
    }
    for (int idx = tid; idx < 32*64; idx += 256) {
        int k = idx >> 6, qq = idx & 63;
        float uv = (c0t + qq < m) ? Up[k*N + (j1 + c0t + qq)] : 0.0f;
        sUu[k*TL_U + qq] = uv;
    }
    __syncthreads();

    const int r0 = r0t + ty*8;
    const int c0 = c0t + tx*4;
    if (r0 < m && c0 < m) {
        const int ra = j1 + r0;
        const int ca = j1 + c0;
        u64 acc[8][2];
        #pragma unroll
        for (int ii = 0; ii < 8; ii++) {
            ulonglong2 v = *reinterpret_cast<const ulonglong2*>(&Mb[(size_t)(ra+ii)*N + ca]);
            acc[ii][0] = v.x; acc[ii][1] = v.y;
        }
        #pragma unroll 8
        for (int k = 0; k < 32; k++) {
            const ulonglong2* ap = reinterpret_cast<const ulonglong2*>(&sLd[k*TL_L + ty*8]);
            ulonglong2 a01 = ap[0], a23 = ap[1], a45 = ap[2], a67 = ap[3];
            ulonglong2 b = *reinterpret_cast<const ulonglong2*>(&sUu[k*TL_U + tx*4]);
            acc[0][0]=ffma2(a01.x,b.x,acc[0][0]); acc[0][1]=ffma2(a01.x,b.y,acc[0][1]);
            acc[1][0]=ffma2(a01.y,b.x,acc[1][0]); acc[1][1]=ffma2(a01.y,b.y,acc[1][1]);
            acc[2][0]=ffma2(a23.x,b.x,acc[2][0]); acc[2][1]=ffma2(a23.x,b.y,acc[2][1]);
            acc[3][0]=ffma2(a23.y,b.x,acc[3][0]); acc[3][1]=ffma2(a23.y,b.y,acc[3][1]);
            acc[4][0]=ffma2(a45.x,b.x,acc[4][0]); acc[4][1]=ffma2(a45.x,b.y,acc[4][1]);
            acc[5][0]=ffma2(a45.y,b.x,acc[5][0]); acc[5][1]=ffma2(a45.y,b.y,acc[5][1]);
            acc[6][0]=ffma2(a67.x,b.x,acc[6][0]); acc[6][1]=ffma2(a67.x,b.y,acc[6][1]);
            acc[7][0]=ffma2(a67.y,b.x,acc[7][0]); acc[7][1]=ffma2(a67.y,b.y,acc[7][1]);
        }
        #pragma unroll
        for (int ii = 0; ii < 8; ii++) {
            ulonglong2 o; o.x = acc[ii][0]; o.y = acc[ii][1];
            *reinterpret_cast<ulonglong2*>(&Mb[(size_t)(ra+ii)*N + ca]) = o;
        }
    }
}

// ---------------- kernel 5: tail LU — trailing 224x224 entirely in smem ----------------
#define TOFF 288
#define TM 224
#define TST 228
#define SMEM_TAIL ((TM*TST + 32*33 + 32) * 4)

__global__ void __launch_bounds__(256) k_tail() {
    extern __shared__ float sA[];
    float* sD    = sA + TM*TST;
    float* sDinv = sD + 32*33;
    const int mat = blockIdx.x;
    const int tid = threadIdx.x;
    const int tx = tid & 15, ty = tid >> 4;
    float* Mb = g_M + (size_t)mat * N2;

    for (int e = tid; e < TM * (TM/4); e += 256) {
        int r = e / (TM/4), c4 = e % (TM/4);
        float4 v = *reinterpret_cast<const float4*>(&Mb[(size_t)(TOFF+r)*N + TOFF + c4*4]);
        *reinterpret_cast<float4*>(&sA[r*TST + c4*4]) = v;
    }
    __syncthreads();

    for (int p = 0; p < 7; p++) {
        const int j0 = p*32, j1 = j0 + 32;
        const int m = TM - j1;

        if (tid < 32) {
            const int lane = tid;
            float v[32];
            #pragma unroll
            for (int c = 0; c < 32; c++) v[c] = sA[(j0+lane)*TST + j0 + c];
            #pragma unroll
            for (int j = 0; j < 32; j++) {
                float diag = __shfl_sync(0xffffffffu, v[j], j);
                float l = v[j] * (1.0f / diag);
                #pragma unroll
                for (int c = j + 1; c < 32; c++) {
                    float ujc = __shfl_sync(0xffffffffu, v[c], j);
                    if (lane > j) v[c] -= l * ujc;
                }
                if (lane > j) v[j] = l;
            }
            float ld = logf(fabsf(v[lane]));
            #pragma unroll
            for (int off = 16; off; off >>= 1) ld += __shfl_xor_sync(0xffffffffu, ld, off);
            if (lane == 0) g_ld[mat*NPAN + 9 + p] = ld;
            #pragma unroll
            for (int c = 0; c < 32; c++) sD[lane*33 + c] = v[c];
            sDinv[lane] = 1.0f / v[lane];
        }
        __syncthreads();
        if (m == 0) break;

        if (tid < m) {
            const int r = j1 + tid;
            float a[32];
            #pragma unroll
            for (int k = 0; k < 32; k++) a[k] = sA[r*TST + j0 + k];
            #pragma unroll
            for (int k = 0; k < 32; k++) {
                float acc = a[k];
                #pragma unroll
                for (int t = 0; t < k; t++) acc -= a[t] * sD[t*33 + k];
                a[k] = acc * sDinv[k];
            }
            #pragma unroll
            for (int k = 0; k < 32; k++) sA[r*TST + j0 + k] = a[k];

            const int c = j1 + tid;
            float y[32];
            #pragma unroll
            for (int k = 0; k < 32; k++) y[k] = sA[(j0+k)*TST + c];
            #pragma unroll
            for (int k = 1; k < 32; k++) {
                float acc = y[k];
                #pragma unroll
                for (int t = 0; t < 32 && t < k; t++) acc -= sD[k*33 + t] * y[t];
                y[k] = acc;
            }
            #pragma unroll
            for (int k = 0; k < 32; k++) sA[(j0+k)*TST + c] = y[k];
        }
        __syncthreads();

        for (int rb = 0; rb < m; rb += 128) {
            for (int cb = 0; cb < m; cb += 128) {
                const int r0 = rb + ty*8, c0 = cb + tx*8;
                if (r0 < m && c0 < m) {
                    float acc[8][8];
                    #pragma unroll
                    for (int ii = 0; ii < 8; ii++) {
                        const float4* cp = reinterpret_cast<const float4*>(
                            &sA[(j1+r0+ii)*TST + j1 + c0]);
                        float4 v0 = cp[0], v1 = cp[1];
                        acc[ii][0]=v0.x; acc[ii][1]=v0.y; acc[ii][2]=v0.z; acc[ii][3]=v0.w;
                        acc[ii][4]=v1.x; acc[ii][5]=v1.y; acc[ii][6]=v1.z; acc[ii][7]=v1.w;
                    }
                    #pragma unroll 4
                    for (int k = 0; k < 32; k++) {
                        const float4* bp = reinterpret_cast<const float4*>(
                            &sA[(j0+k)*TST + j1 + c0]);
                        float4 b0 = bp[0], b1 = bp[1];
                        float bf[8] = {b0.x,b0.y,b0.z,b0.w,b1.x,b1.y,b1.z,b1.w};
                        #pragma unroll
                        for (int ii = 0; ii < 8; ii++) {
                            float na = -sA[(j1+r0+ii)*TST + j0 + k];
                            #pragma unroll
                            for (int jj = 0; jj < 8; jj++)
                                acc[ii][jj] = fmaf(na, bf[jj], acc[ii][jj]);
                        }
                    }
                    #pragma unroll
                    for (int ii = 0; ii < 8; ii++) {
                        float4* cp = reinterpret_cast<float4*>(
                            &sA[(j1+r0+ii)*TST + j1 + c0]);
                        float4 o0 = make_float4(acc[ii][0],acc[ii][1],acc[ii][2],acc[ii][3]);
                        float4 o1 = make_float4(acc[ii][4],acc[ii][5],acc[ii][6],acc[ii][7]);
                        cp[0] = o0; cp[1] = o1;
                    }
                }
            }
        }
        __syncthreads();
    }
}

// ---------------- kernel 6: combine ----------------
__global__ void k_final(const int* __restrict__ x, const float* __restrict__ Vc,
                        float* __restrict__ out) {
    __shared__ float red[256];
    int b = blockIdx.x, tid = threadIdx.x;
    float s = 0.0f;
    for (int i = tid; i < N; i += 256) {
        int xi = x[b*N + i];
        float a0 = Vc[2*i], a1 = Vc[2*i+1];
        float m = fmaxf(a0, a1);
        float lse = m + logf(expf(a0 - m) + expf(a1 - m));
        s += (xi ? a1 : a0) - lse;
    }
    red[tid] = s;
    __syncthreads();
    #pragma unroll
    for (int o = 128; o; o >>= 1) {
        if (tid < o) red[tid] += red[tid + o];
        __syncthreads();
    }
    if (tid == 0) {
        float ld = 0.0f;
        #pragma unroll
        for (int k = 0; k < NPAN; k++)
            ld += g_ld[b*NPAN + k] - g_ld[BATCH*NPAN + k];
        out[b] = red[0] + ld;
    }
}

// ---------------- launcher ----------------
extern "C" void kernel_launch(void* const* d_in, const int* in_sizes, int n_in,
                              void* d_out, int out_size) {
    const int* x = nullptr;
    const float* W = nullptr;
    const float* Vc = nullptr;
    const float* Ec = nullptr;
    for (int k = 0; k < n_in; k++) {
        switch (in_sizes[k]) {
            case BATCH * N:   x  = (const int*)d_in[k];   break;  // 65536
            case N * N:       W  = (const float*)d_in[k]; break;  // 262144
            case N * 2:       Vc = (const float*)d_in[k]; break;  // 1024
            case N * N * 4:   Ec = (const float*)d_in[k]; break;  // 1048576
        }
    }
    float* out = (float*)d_out;

    cudaFuncSetAttribute(k_update64, cudaFuncAttributeMaxDynamicSharedMemorySize, SMEM_U64);
    cudaFuncSetAttribute(k_update,   cudaFuncAttributeMaxDynamicSharedMemorySize, SMEM_UPD);
    cudaFuncSetAttribute(k_tail,     cudaFuncAttributeMaxDynamicSharedMemorySize, SMEM_TAIL);

    k_ipf<<<N2 / 256, 256>>>(W, Vc, Ec);
    k_build<<<NMAT, 512>>>(x, W);
    for (int p = 0; p < 4; p++) {
        dim3 pg(NMAT, 4);
        k_panel<<<pg, 256>>>(2*p);            // panel A of the pair (j0 = 64p)
        k_panelB<<<pg, 256>>>(p);             // panel B fused     (j0 = 64p+32)
        int m = N - (64*p + 64);
        dim3 ug(NMAT, (m + 127)/128, m/64);
        k_update64<<<ug, 256, SMEM_U64>>>(p); // rank-64 trailing update
    }
    {
        dim3 pg(NMAT, 4);
        k_panel<<<pg, 256>>>(8);              // panel 8 (j0 = 256)
        int m = N - 288;
        dim3 ug(NMAT, (m + 127)/128, (m + 63)/64);
        k_update<<<ug, 256, SMEM_UPD>>>(8);   // rank-32 update into the tail block
    }
    k_tail<<<NMAT, 256, SMEM_TAIL>>>();
    k_final<<<BATCH, 256>>>(x, Vc, out);
}